// round 14
// baseline (speedup 1.0000x reference)
#include <cuda_runtime.h>
#include <cuda_bf16.h>

typedef unsigned long long ull;

// Problem shapes (fixed)
#define BN 16
#define FN 4096
#define MN 512
#define DN 256
#define VEN 64
#define HN 512
#define OUTN 8
#define VN 50
#define INW 320          // VEN + DN
#define NSEG 8192        // BN * MN

#define NPB 512          // proj main blocks (4096 warps x 16 frames = 65536 frames)
#define FRPW 16          // frames per warp (contiguous)

// ---------------------------------------------------------------------------
// One contiguous scratch array (single memset node zeroes [0, OFF_PE)).
//   sum   [NSEG*8]  @ 0        cnt [NSEG] @ 65536
//   Wf    [2048]    @ 73728    k-major ull view: ull[k*128+jp] = (Wc[64+2jp][k], Wc[64+2jp+1][k])
//   WcEmb [512]     @ 75776    bc [8] @ 76288    pe [400] @ 76296
// ---------------------------------------------------------------------------
#define OFF_SUM   0
#define OFF_CNT   65536
#define OFF_WF    73728
#define OFF_WCEMB 75776
#define OFF_BC    76288
#define OFF_PE    76296
#define SCR_TOTAL 76704

__device__ __align__(16) float g_scr[SCR_TOTAL];

__device__ __forceinline__ ull fma2(ull a, ull b, ull c) {
    ull d;
    asm("fma.rn.f32x2 %0, %1, %2, %3;" : "=l"(d) : "l"(a), "l"(b), "l"(c));
    return d;
}
__device__ __forceinline__ ull add2(ull a, ull b) {
    ull d;
    asm("add.rn.f32x2 %0, %1, %2;" : "=l"(d) : "l"(a), "l"(b));
    return d;
}

// ---------------------------------------------------------------------------
// Transposed warp reduction: v[0..7] per lane (k partials) -> each lane
// returns the full warp sum for k = lane & 7. 9 shuffles.
// ---------------------------------------------------------------------------
__device__ __forceinline__ float warp_reduce_k(const float v[8], int lane) {
    const unsigned FULL = 0xFFFFFFFFu;
    float nv[4];
    const int b0 = lane & 1;
#pragma unroll
    for (int i = 0; i < 4; i++) {
        float keep = b0 ? v[2 * i + 1] : v[2 * i];
        float send = b0 ? v[2 * i]     : v[2 * i + 1];
        nv[i] = keep + __shfl_xor_sync(FULL, send, 1);
    }
    const int b1 = (lane >> 1) & 1;
    float mv[2];
#pragma unroll
    for (int i = 0; i < 2; i++) {
        float keep = b1 ? nv[2 * i + 1] : nv[2 * i];
        float send = b1 ? nv[2 * i]     : nv[2 * i + 1];
        mv[i] = keep + __shfl_xor_sync(FULL, send, 2);
    }
    const int b2 = (lane >> 2) & 1;
    float keep = b2 ? mv[1] : mv[0];
    float send = b2 ? mv[0] : mv[1];
    float s = keep + __shfl_xor_sync(FULL, send, 4);
    s += __shfl_xor_sync(FULL, s, 8);
    s += __shfl_xor_sync(FULL, s, 16);
    return s;   // k = lane & 7
}

// ---------------------------------------------------------------------------
// Kernel A: fold Wc = W_mora @ W_post + bc. Warp-per-(row, H-half): 642 warps.
// No smem, no barrier; W_post read direct (L2-hot); atomicAdd into zeroed scr.
// ---------------------------------------------------------------------------
__global__ __launch_bounds__(256) void fold_kernel(
    const float* __restrict__ W_mora,   // [320, 512]
    const float* __restrict__ b_mora,   // [512]
    const float* __restrict__ W_post,   // [512, 8]
    const float* __restrict__ b_post)   // [8]
{
    const int tid = threadIdx.x;
    const int lane = tid & 31;
    const int w = blockIdx.x * 8 + (tid >> 5);   // 0..647
    const int i = w >> 1;                        // row 0..323
    const int half = w & 1;
    if (i > INW) return;

    const float* src = (i < INW) ? (W_mora + (size_t)i * HN) : b_mora;

    float acc[8];
#pragma unroll
    for (int k = 0; k < 8; k++) acc[k] = 0.0f;

#pragma unroll
    for (int j = 0; j < 8; j++) {
        const int h = half * 256 + 32 * j + lane;
        const float a = src[h];
        const float4* wp = (const float4*)(W_post + h * OUTN);
        float4 p0 = wp[0], p1 = wp[1];
        acc[0] += a * p0.x; acc[1] += a * p0.y; acc[2] += a * p0.z; acc[3] += a * p0.w;
        acc[4] += a * p1.x; acc[5] += a * p1.y; acc[6] += a * p1.z; acc[7] += a * p1.w;
    }

    float s = warp_reduce_k(acc, lane);
    if (lane < 8) {
        const int k = lane;
        if (i < VEN) {
            atomicAdd(g_scr + OFF_WCEMB + i * OUTN + k, s);
        } else if (i < INW) {
            const int j = i - VEN;
            atomicAdd(g_scr + OFF_WF + (k * 128 + (j >> 1)) * 2 + (j & 1), s);
        } else {
            atomicAdd(g_scr + OFF_BC + k, s + (half == 0 ? b_post[k] : 0.0f));
        }
    }
}

// ---------------------------------------------------------------------------
// Flush: project 8-per-lane run-sum (racc, 4 f32x2) to 8 outputs using smem
// weights (k-major, conflict-free LDS.128), transposed reduce, atomic scatter.
// ---------------------------------------------------------------------------
__device__ __noinline__ void flush_seg(const ull* __restrict__ sWf,
                                       const ull* __restrict__ racc,
                                       float fcnt, int seg, int lane) {
    const int p0 = 2 * lane, p1 = 64 + 2 * lane;
    float v[8];
#pragma unroll
    for (int k = 0; k < 8; k++) {
        ulonglong2 wa = *(const ulonglong2*)(sWf + k * 128 + p0);
        ulonglong2 wb = *(const ulonglong2*)(sWf + k * 128 + p1);
        ull t = fma2(racc[0], wa.x,
                fma2(racc[1], wa.y,
                fma2(racc[2], wb.x,
                fma2(racc[3], wb.y, 0ull))));
        float lo = __int_as_float((int)(t & 0xFFFFFFFFull));
        float hi = __int_as_float((int)(t >> 32));
        v[k] = lo + hi;
    }
    float s = warp_reduce_k(v, lane);
    if (lane < 8) atomicAdd(g_scr + OFF_SUM + seg * OUTN + lane, s);
    else if (lane == 8) atomicAdd(g_scr + OFF_CNT + seg, fcnt);
}

// ---------------------------------------------------------------------------
// Kernel B: per-frame 8-dim-per-lane running sums, 3-deep software-pipelined
// loads: 2 batches (16 LDG.128, 8 KB/warp) stay in flight while one batch is
// consumed. Extra blocks compute pe.
// ---------------------------------------------------------------------------
__global__ __launch_bounds__(256) void proj_kernel(
    const float* __restrict__ features,   // [B, F, D]
    const int* __restrict__ mora_index,   // [B, F]
    const float* __restrict__ emb_table)  // [V, VE]
{
    const unsigned FULL = 0xFFFFFFFFu;

    if (blockIdx.x >= NPB) {
        // per-vowel embedding projection: pe[v][k] = emb[v] . WcEmb[:,k]
        const int gt = (blockIdx.x - NPB) * 256 + threadIdx.x;  // 2 blocks >= 400
        if (gt < VN * OUTN) {
            const int v = gt >> 3, k = gt & 7;
            const float* e = emb_table + v * VEN;
            float s = 0.0f;
#pragma unroll 8
            for (int j = 0; j < VEN; j++) s += e[j] * g_scr[OFF_WCEMB + j * OUTN + k];
            g_scr[OFF_PE + gt] = s;
        }
        return;
    }

    __shared__ __align__(16) ull sWf[128 * 8];   // 8 KB, k-major
    const int tid = threadIdx.x;
    for (int j = tid; j < 128 * 8 / 2; j += 256)
        ((ulonglong2*)sWf)[j] = ((const ulonglong2*)(g_scr + OFF_WF))[j];
    __syncthreads();

    const int lane = tid & 31;
    const int warp = (blockIdx.x * 256 + tid) >> 5;   // 0..4095
    const int base = warp * FRPW;                     // 16 contiguous frames
    const int b = base >> 12;                         // / FN

    // preload the 16 mora indices for this warp (one coalesced LDG)
    const int myidx = mora_index[base + (lane & 15)];

    ull racc[4];
#pragma unroll
    for (int q = 0; q < 4; q++) racc[q] = 0ull;
    float fcnt = 0.0f;
    int curm = __shfl_sync(FULL, myidx, 0);

    const ulonglong2* fr = (const ulonglong2*)(features + (size_t)base * DN);

    // 3-deep software pipeline over 4 batches of 4 frames:
    // batches bt+1 and bt+2 are in flight while batch bt is consumed.
    ulonglong2 xa[3][4], xb[3][4];
#pragma unroll
    for (int s = 0; s < 2; s++) {
#pragma unroll
        for (int j = 0; j < 4; j++) {
            xa[s][j] = fr[(s * 4 + j) * 64 + lane];        // dims 4l..4l+3
            xb[s][j] = fr[(s * 4 + j) * 64 + 32 + lane];   // dims 128+4l..
        }
    }

#pragma unroll
    for (int bt = 0; bt < 4; bt++) {
        const int cs = bt % 3;
        if (bt < 2) {
            const int ns = (bt + 2) % 3;
            // issue batch bt+2's 8 LDG.128 before consuming batch bt
#pragma unroll
            for (int j = 0; j < 4; j++) {
                xa[ns][j] = fr[((bt + 2) * 4 + j) * 64 + lane];
                xb[ns][j] = fr[((bt + 2) * 4 + j) * 64 + 32 + lane];
            }
        }
#pragma unroll
        for (int j = 0; j < 4; j++) {
            const int m = __shfl_sync(FULL, myidx, bt * 4 + j);
            if (m != curm) {                          // warp-uniform
                flush_seg(sWf, racc, fcnt, (b << 9) + curm, lane);
#pragma unroll
                for (int q = 0; q < 4; q++) racc[q] = 0ull;
                fcnt = 0.0f;
                curm = m;
            }
            racc[0] = add2(racc[0], xa[cs][j].x);
            racc[1] = add2(racc[1], xa[cs][j].y);
            racc[2] = add2(racc[2], xb[cs][j].x);
            racc[3] = add2(racc[3], xb[cs][j].y);
            fcnt += 1.0f;
        }
    }
    flush_seg(sWf, racc, fcnt, (b << 9) + curm, lane);
}

// ---------------------------------------------------------------------------
// Kernel C: finalize, thread-per-row, vectorized:
// out[row][k] = bc[k] + pe[vowel][k] + sum[row][k] * (cnt>0 ? 1/cnt : 0)
// ---------------------------------------------------------------------------
__global__ __launch_bounds__(256) void final_kernel(
    const int* __restrict__ vowels,       // [B, M]
    float* __restrict__ out)              // [B, M, 8]
{
    const int row = blockIdx.x * blockDim.x + threadIdx.x;
    if (row >= NSEG) return;

    const int v = vowels[row];
    const float4 b0 = ((const float4*)(g_scr + OFF_BC))[0];
    const float4 b1 = ((const float4*)(g_scr + OFF_BC))[1];
    const float4 p0 = ((const float4*)(g_scr + OFF_PE))[v * 2];
    const float4 p1 = ((const float4*)(g_scr + OFF_PE))[v * 2 + 1];
    const float4 s0 = ((const float4*)(g_scr + OFF_SUM))[row * 2];
    const float4 s1 = ((const float4*)(g_scr + OFF_SUM))[row * 2 + 1];
    const float cnt = g_scr[OFF_CNT + row];
    const float inv = (cnt > 0.0f) ? (1.0f / cnt) : 0.0f;

    float4 o0, o1;
    o0.x = b0.x + p0.x + s0.x * inv; o0.y = b0.y + p0.y + s0.y * inv;
    o0.z = b0.z + p0.z + s0.z * inv; o0.w = b0.w + p0.w + s0.w * inv;
    o1.x = b1.x + p1.x + s1.x * inv; o1.y = b1.y + p1.y + s1.y * inv;
    o1.z = b1.z + p1.z + s1.z * inv; o1.w = b1.w + p1.w + s1.w * inv;

    ((float4*)out)[row * 2]     = o0;
    ((float4*)out)[row * 2 + 1] = o1;
}

// ---------------------------------------------------------------------------
// launch: memset + fold + proj(+pe) + final
// ---------------------------------------------------------------------------
extern "C" void kernel_launch(void* const* d_in, const int* in_sizes, int n_in,
                              void* d_out, int out_size)
{
    const int*   vowels     = (const int*)d_in[0];
    const float* features   = (const float*)d_in[1];
    const int*   mora_index = (const int*)d_in[2];
    const float* emb_table  = (const float*)d_in[3];
    const float* W_mora     = (const float*)d_in[4];
    const float* b_mora     = (const float*)d_in[5];
    // d_in[6] = W_frame, d_in[7] = b_frame: dead branch, unused
    const float* W_post     = (const float*)d_in[8];
    const float* b_post     = (const float*)d_in[9];
    float* out = (float*)d_out;

    // single memset node zeroes sum/cnt/Wf/WcEmb/bc (fold uses atomicAdd)
    void* p_scr = nullptr;
    cudaGetSymbolAddress(&p_scr, g_scr);
    cudaMemsetAsync(p_scr, 0, OFF_PE * sizeof(float));

    fold_kernel<<<81, 256>>>(W_mora, b_mora, W_post, b_post);
    proj_kernel<<<NPB + 2, 256>>>(features, mora_index, emb_table);
    final_kernel<<<(NSEG + 255) / 256, 256>>>(vowels, out);
}

// round 15
// speedup vs baseline: 1.2653x; 1.2653x over previous
#include <cuda_runtime.h>
#include <cuda_bf16.h>

typedef unsigned long long ull;

// Problem shapes (fixed)
#define BN 16
#define FN 4096
#define MN 512
#define DN 256
#define VEN 64
#define HN 512
#define OUTN 8
#define VN 50
#define INW 320          // VEN + DN
#define NSEG 8192        // BN * MN

#define NPB 1024         // proj main blocks: 8192 warps = 4096 chunks x 2 halves
#define FRPW 16          // frames per chunk (contiguous)

// ---------------------------------------------------------------------------
// One contiguous scratch array (single memset node zeroes [0, OFF_PE)).
//   sum   [NSEG*8]  @ 0        cnt [NSEG] @ 65536
//   Wf    [2048]    @ 73728    k-major ull view: ull[k*128+jp] = (Wc[64+2jp][k], Wc[64+2jp+1][k])
//   WcEmb [512]     @ 75776    bc [8] @ 76288    pe [400] @ 76296
// ---------------------------------------------------------------------------
#define OFF_SUM   0
#define OFF_CNT   65536
#define OFF_WF    73728
#define OFF_WCEMB 75776
#define OFF_BC    76288
#define OFF_PE    76296
#define SCR_TOTAL 76704

__device__ __align__(16) float g_scr[SCR_TOTAL];

__device__ __forceinline__ ull fma2(ull a, ull b, ull c) {
    ull d;
    asm("fma.rn.f32x2 %0, %1, %2, %3;" : "=l"(d) : "l"(a), "l"(b), "l"(c));
    return d;
}
__device__ __forceinline__ ull add2(ull a, ull b) {
    ull d;
    asm("add.rn.f32x2 %0, %1, %2;" : "=l"(d) : "l"(a), "l"(b));
    return d;
}

// ---------------------------------------------------------------------------
// Transposed warp reduction: v[0..7] per lane (k partials) -> each lane
// returns the full warp sum for k = lane & 7. 9 shuffles.
// ---------------------------------------------------------------------------
__device__ __forceinline__ float warp_reduce_k(const float v[8], int lane) {
    const unsigned FULL = 0xFFFFFFFFu;
    float nv[4];
    const int b0 = lane & 1;
#pragma unroll
    for (int i = 0; i < 4; i++) {
        float keep = b0 ? v[2 * i + 1] : v[2 * i];
        float send = b0 ? v[2 * i]     : v[2 * i + 1];
        nv[i] = keep + __shfl_xor_sync(FULL, send, 1);
    }
    const int b1 = (lane >> 1) & 1;
    float mv[2];
#pragma unroll
    for (int i = 0; i < 2; i++) {
        float keep = b1 ? nv[2 * i + 1] : nv[2 * i];
        float send = b1 ? nv[2 * i]     : nv[2 * i + 1];
        mv[i] = keep + __shfl_xor_sync(FULL, send, 2);
    }
    const int b2 = (lane >> 2) & 1;
    float keep = b2 ? mv[1] : mv[0];
    float send = b2 ? mv[0] : mv[1];
    float s = keep + __shfl_xor_sync(FULL, send, 4);
    s += __shfl_xor_sync(FULL, s, 8);
    s += __shfl_xor_sync(FULL, s, 16);
    return s;   // k = lane & 7
}

// ---------------------------------------------------------------------------
// Kernel A: fold Wc = W_mora @ W_post + bc. Warp-per-(row, H-half): 642 warps.
// No smem, no barrier; W_post read direct (L2-hot); atomicAdd into zeroed scr.
// ---------------------------------------------------------------------------
__global__ __launch_bounds__(256) void fold_kernel(
    const float* __restrict__ W_mora,   // [320, 512]
    const float* __restrict__ b_mora,   // [512]
    const float* __restrict__ W_post,   // [512, 8]
    const float* __restrict__ b_post)   // [8]
{
    const int tid = threadIdx.x;
    const int lane = tid & 31;
    const int w = blockIdx.x * 8 + (tid >> 5);   // 0..647
    const int i = w >> 1;                        // row 0..323
    const int half = w & 1;
    if (i > INW) return;

    const float* src = (i < INW) ? (W_mora + (size_t)i * HN) : b_mora;

    float acc[8];
#pragma unroll
    for (int k = 0; k < 8; k++) acc[k] = 0.0f;

#pragma unroll
    for (int j = 0; j < 8; j++) {
        const int h = half * 256 + 32 * j + lane;
        const float a = src[h];
        const float4* wp = (const float4*)(W_post + h * OUTN);
        float4 p0 = wp[0], p1 = wp[1];
        acc[0] += a * p0.x; acc[1] += a * p0.y; acc[2] += a * p0.z; acc[3] += a * p0.w;
        acc[4] += a * p1.x; acc[5] += a * p1.y; acc[6] += a * p1.z; acc[7] += a * p1.w;
    }

    float s = warp_reduce_k(acc, lane);
    if (lane < 8) {
        const int k = lane;
        if (i < VEN) {
            atomicAdd(g_scr + OFF_WCEMB + i * OUTN + k, s);
        } else if (i < INW) {
            const int j = i - VEN;
            atomicAdd(g_scr + OFF_WF + (k * 128 + (j >> 1)) * 2 + (j & 1), s);
        } else {
            atomicAdd(g_scr + OFF_BC + k, s + (half == 0 ? b_post[k] : 0.0f));
        }
    }
}

// ---------------------------------------------------------------------------
// Flush (half-frame variant): project this warp's 4-per-lane run-sum (2 f32x2,
// covering dims [half*128, half*128+128)) with its half of the smem weights,
// transposed reduce, atomic scatter. cnt added by half 0 only.
// ---------------------------------------------------------------------------
__device__ __noinline__ void flush_half(const ull* __restrict__ sWf,
                                        const ull* __restrict__ racc,
                                        float fcnt, int seg, int lane, int half) {
    const int jp = half * 64 + 2 * lane;
    float v[8];
#pragma unroll
    for (int k = 0; k < 8; k++) {
        ulonglong2 wa = *(const ulonglong2*)(sWf + k * 128 + jp);
        ull t = fma2(racc[0], wa.x, fma2(racc[1], wa.y, 0ull));
        float lo = __int_as_float((int)(t & 0xFFFFFFFFull));
        float hi = __int_as_float((int)(t >> 32));
        v[k] = lo + hi;
    }
    float s = warp_reduce_k(v, lane);
    if (lane < 8) atomicAdd(g_scr + OFF_SUM + seg * OUTN + lane, s);
    else if (lane == 8 && half == 0) atomicAdd(g_scr + OFF_CNT + seg, fcnt);
}

// ---------------------------------------------------------------------------
// Kernel B: warp pair per 16-frame chunk (half 0: dims 0-127, half 1: 128-255).
// 1 LDG.128 per frame per lane; 8-frame batches, 2-deep software pipeline
// (8-16 LDG.128 in flight per warp at only ~32 buffer regs). Extra blocks pe.
// ---------------------------------------------------------------------------
__global__ __launch_bounds__(256) void proj_kernel(
    const float* __restrict__ features,   // [B, F, D]
    const int* __restrict__ mora_index,   // [B, F]
    const float* __restrict__ emb_table)  // [V, VE]
{
    const unsigned FULL = 0xFFFFFFFFu;

    if (blockIdx.x >= NPB) {
        // per-vowel embedding projection: pe[v][k] = emb[v] . WcEmb[:,k]
        const int gt = (blockIdx.x - NPB) * 256 + threadIdx.x;  // 2 blocks >= 400
        if (gt < VN * OUTN) {
            const int v = gt >> 3, k = gt & 7;
            const float* e = emb_table + v * VEN;
            float s = 0.0f;
#pragma unroll 8
            for (int j = 0; j < VEN; j++) s += e[j] * g_scr[OFF_WCEMB + j * OUTN + k];
            g_scr[OFF_PE + gt] = s;
        }
        return;
    }

    __shared__ __align__(16) ull sWf[128 * 8];   // 8 KB, k-major
    const int tid = threadIdx.x;
    for (int j = tid; j < 128 * 8 / 2; j += 256)
        ((ulonglong2*)sWf)[j] = ((const ulonglong2*)(g_scr + OFF_WF))[j];
    __syncthreads();

    const int lane = tid & 31;
    const int gw = (blockIdx.x * 256 + tid) >> 5;   // 0..8191
    const int chunk = gw >> 1;                      // 0..4095
    const int half = gw & 1;                        // dim half
    const int base = chunk * FRPW;                  // 16 contiguous frames
    const int b = base >> 12;                       // / FN

    // preload the 16 mora indices for this chunk (one coalesced LDG)
    const int myidx = mora_index[base + (lane & 15)];

    ull racc[2];
    racc[0] = racc[1] = 0ull;
    float fcnt = 0.0f;
    int curm = __shfl_sync(FULL, myidx, 0);

    // lane covers dims [half*128 + 4*lane, +4): one ulonglong2 per frame
    const ulonglong2* fr =
        (const ulonglong2*)(features + (size_t)base * DN + half * 128);

    // 2-deep software pipeline over 2 batches of 8 frames
    ulonglong2 x[2][8];
#pragma unroll
    for (int j = 0; j < 8; j++) x[0][j] = fr[j * 64 + lane];

#pragma unroll
    for (int bt = 0; bt < 2; bt++) {
        if (bt == 0) {
            // issue batch 1's 8 LDG.128 before consuming batch 0
#pragma unroll
            for (int j = 0; j < 8; j++) x[1][j] = fr[(8 + j) * 64 + lane];
        }
#pragma unroll
        for (int j = 0; j < 8; j++) {
            const int m = __shfl_sync(FULL, myidx, bt * 8 + j);
            if (m != curm) {                          // warp-uniform
                flush_half(sWf, racc, fcnt, (b << 9) + curm, lane, half);
                racc[0] = racc[1] = 0ull;
                fcnt = 0.0f;
                curm = m;
            }
            racc[0] = add2(racc[0], x[bt][j].x);
            racc[1] = add2(racc[1], x[bt][j].y);
            fcnt += 1.0f;
        }
    }
    flush_half(sWf, racc, fcnt, (b << 9) + curm, lane, half);
}

// ---------------------------------------------------------------------------
// Kernel C: finalize, thread-per-row, vectorized:
// out[row][k] = bc[k] + pe[vowel][k] + sum[row][k] * (cnt>0 ? 1/cnt : 0)
// ---------------------------------------------------------------------------
__global__ __launch_bounds__(256) void final_kernel(
    const int* __restrict__ vowels,       // [B, M]
    float* __restrict__ out)              // [B, M, 8]
{
    const int row = blockIdx.x * blockDim.x + threadIdx.x;
    if (row >= NSEG) return;

    const int v = vowels[row];
    const float4 b0 = ((const float4*)(g_scr + OFF_BC))[0];
    const float4 b1 = ((const float4*)(g_scr + OFF_BC))[1];
    const float4 p0 = ((const float4*)(g_scr + OFF_PE))[v * 2];
    const float4 p1 = ((const float4*)(g_scr + OFF_PE))[v * 2 + 1];
    const float4 s0 = ((const float4*)(g_scr + OFF_SUM))[row * 2];
    const float4 s1 = ((const float4*)(g_scr + OFF_SUM))[row * 2 + 1];
    const float cnt = g_scr[OFF_CNT + row];
    const float inv = (cnt > 0.0f) ? (1.0f / cnt) : 0.0f;

    float4 o0, o1;
    o0.x = b0.x + p0.x + s0.x * inv; o0.y = b0.y + p0.y + s0.y * inv;
    o0.z = b0.z + p0.z + s0.z * inv; o0.w = b0.w + p0.w + s0.w * inv;
    o1.x = b1.x + p1.x + s1.x * inv; o1.y = b1.y + p1.y + s1.y * inv;
    o1.z = b1.z + p1.z + s1.z * inv; o1.w = b1.w + p1.w + s1.w * inv;

    ((float4*)out)[row * 2]     = o0;
    ((float4*)out)[row * 2 + 1] = o1;
}

// ---------------------------------------------------------------------------
// launch: memset + fold + proj(+pe) + final
// ---------------------------------------------------------------------------
extern "C" void kernel_launch(void* const* d_in, const int* in_sizes, int n_in,
                              void* d_out, int out_size)
{
    const int*   vowels     = (const int*)d_in[0];
    const float* features   = (const float*)d_in[1];
    const int*   mora_index = (const int*)d_in[2];
    const float* emb_table  = (const float*)d_in[3];
    const float* W_mora     = (const float*)d_in[4];
    const float* b_mora     = (const float*)d_in[5];
    // d_in[6] = W_frame, d_in[7] = b_frame: dead branch, unused
    const float* W_post     = (const float*)d_in[8];
    const float* b_post     = (const float*)d_in[9];
    float* out = (float*)d_out;

    // single memset node zeroes sum/cnt/Wf/WcEmb/bc (fold uses atomicAdd)
    void* p_scr = nullptr;
    cudaGetSymbolAddress(&p_scr, g_scr);
    cudaMemsetAsync(p_scr, 0, OFF_PE * sizeof(float));

    fold_kernel<<<81, 256>>>(W_mora, b_mora, W_post, b_post);
    proj_kernel<<<NPB + 2, 256>>>(features, mora_index, emb_table);
    final_kernel<<<(NSEG + 255) / 256, 256>>>(vowels, out);
}